// round 4
// baseline (speedup 1.0000x reference)
#include <cuda_runtime.h>
#include <math.h>

#define S_LEN 8192
#define DIM   1024
#define NH    16
#define HD    64
#define WIN   512

// Scratch (static device globals: allocation-free rule)
__device__ float g_q[S_LEN * DIM];
__device__ float g_k[S_LEN * DIM];
__device__ float g_v[S_LEN * DIM];
__device__ float g_o[S_LEN * DIM];

// ---------------------------------------------------------------------------
// SGEMM NT: C[M,N] = A[M,K] * B[N,K]^T   (both row-major, K contiguous)
// 128x128 block tile, BK=8, 256 threads, 8x8 microtile (4+4 split fragments).
// Double-buffered smem: one __syncthreads per k-step, LDG issued before the
// compute of the previous tile so L2 latency hides under 256 FMA-issue cycles.
// NMAT=3 fuses the Q/K/V projections via blockIdx.z.
// ---------------------------------------------------------------------------
template <int NMAT>
__global__ __launch_bounds__(256) void sgemm_nt(
    const float* __restrict__ A,
    const float* __restrict__ B0, const float* __restrict__ B1,
    const float* __restrict__ B2,
    float* __restrict__ C0, float* __restrict__ C1, float* __restrict__ C2,
    int M, int N, int K)
{
    const float* B = B0;
    float* C = C0;
    if (NMAT == 3) {
        if (blockIdx.z == 1) { B = B1; C = C1; }
        else if (blockIdx.z == 2) { B = B2; C = C2; }
    }

    __shared__ float As[2][8][128];   // [buf][k][m]
    __shared__ float Bs[2][8][128];   // [buf][k][n]

    const int t  = threadIdx.x;
    const int tx = t & 15;
    const int ty = t >> 4;
    const int bm = blockIdx.y * 128;
    const int bn = blockIdx.x * 128;
    const int lr  = t >> 1;          // tile row for loading (0..127)
    const int lc4 = (t & 1) * 4;     // k-offset group (0 or 4)

    float acc[8][8];
#pragma unroll
    for (int i = 0; i < 8; i++)
#pragma unroll
        for (int j = 0; j < 8; j++) acc[i][j] = 0.0f;

    const float* Aptr = A + (size_t)(bm + lr) * K + lc4;
    const float* Bptr = B + (size_t)(bn + lr) * K + lc4;

    // Prologue: load k0=0 into buffer 0
    float4 av = *(const float4*)(Aptr);
    float4 bv = *(const float4*)(Bptr);
    As[0][lc4 + 0][lr] = av.x; As[0][lc4 + 1][lr] = av.y;
    As[0][lc4 + 2][lr] = av.z; As[0][lc4 + 3][lr] = av.w;
    Bs[0][lc4 + 0][lr] = bv.x; Bs[0][lc4 + 1][lr] = bv.y;
    Bs[0][lc4 + 2][lr] = bv.z; Bs[0][lc4 + 3][lr] = bv.w;
    __syncthreads();

    int buf = 0;
    for (int k0 = 8; k0 < K; k0 += 8) {
        // Issue next tile's gmem loads first (latency hides under compute)
        float4 an = *(const float4*)(Aptr + k0);
        float4 bn2 = *(const float4*)(Bptr + k0);

        // Compute on current buffer
#pragma unroll
        for (int kk = 0; kk < 8; kk++) {
            float4 a0 = *(const float4*)&As[buf][kk][ty * 4];
            float4 a1 = *(const float4*)&As[buf][kk][64 + ty * 4];
            float4 b0 = *(const float4*)&Bs[buf][kk][tx * 4];
            float4 b1 = *(const float4*)&Bs[buf][kk][64 + tx * 4];
            float a[8] = {a0.x, a0.y, a0.z, a0.w, a1.x, a1.y, a1.z, a1.w};
            float b[8] = {b0.x, b0.y, b0.z, b0.w, b1.x, b1.y, b1.z, b1.w};
#pragma unroll
            for (int i = 0; i < 8; i++)
#pragma unroll
                for (int j = 0; j < 8; j++)
                    acc[i][j] = fmaf(a[i], b[j], acc[i][j]);
        }

        // Store next tile into the alternate buffer
        int nb = buf ^ 1;
        As[nb][lc4 + 0][lr] = an.x; As[nb][lc4 + 1][lr] = an.y;
        As[nb][lc4 + 2][lr] = an.z; As[nb][lc4 + 3][lr] = an.w;
        Bs[nb][lc4 + 0][lr] = bn2.x; Bs[nb][lc4 + 1][lr] = bn2.y;
        Bs[nb][lc4 + 2][lr] = bn2.z; Bs[nb][lc4 + 3][lr] = bn2.w;
        __syncthreads();
        buf = nb;
    }

    // Epilogue compute on last buffer
#pragma unroll
    for (int kk = 0; kk < 8; kk++) {
        float4 a0 = *(const float4*)&As[buf][kk][ty * 4];
        float4 a1 = *(const float4*)&As[buf][kk][64 + ty * 4];
        float4 b0 = *(const float4*)&Bs[buf][kk][tx * 4];
        float4 b1 = *(const float4*)&Bs[buf][kk][64 + tx * 4];
        float a[8] = {a0.x, a0.y, a0.z, a0.w, a1.x, a1.y, a1.z, a1.w};
        float b[8] = {b0.x, b0.y, b0.z, b0.w, b1.x, b1.y, b1.z, b1.w};
#pragma unroll
        for (int i = 0; i < 8; i++)
#pragma unroll
            for (int j = 0; j < 8; j++)
                acc[i][j] = fmaf(a[i], b[j], acc[i][j]);
    }

#pragma unroll
    for (int i = 0; i < 8; i++) {
        int r = bm + ty * 4 + (i & 3) + ((i >> 2) << 6);
        float4 o0 = make_float4(acc[i][0], acc[i][1], acc[i][2], acc[i][3]);
        float4 o1 = make_float4(acc[i][4], acc[i][5], acc[i][6], acc[i][7]);
        *(float4*)(C + (size_t)r * N + bn + tx * 4)      = o0;
        *(float4*)(C + (size_t)r * N + bn + 64 + tx * 4) = o1;
    }
}

// ---------------------------------------------------------------------------
// RoPE (interleaved pairs) applied in-place to q and k.
// Replicates the reference fp32 computation path.
// ---------------------------------------------------------------------------
__global__ void rope_kernel(float* __restrict__ q, float* __restrict__ k)
{
    int idx = blockIdx.x * blockDim.x + threadIdx.x;
    if (idx >= S_LEN * NH * (HD / 2)) return;
    int j = idx & 31;            // freq index 0..31
    int h = (idx >> 5) & 15;
    int s = idx >> 9;

    float inv_freq = 1.0f / powf(10000.0f, (float)(2 * j) * (1.0f / 64.0f));
    float ang = (float)s * inv_freq;
    float c = cosf(ang), sn = sinf(ang);

    int base = s * DIM + h * HD + 2 * j;
    {
        float x1 = q[base], x2 = q[base + 1];
        q[base]     = x1 * c - x2 * sn;
        q[base + 1] = x1 * sn + x2 * c;
    }
    {
        float x1 = k[base], x2 = k[base + 1];
        k[base]     = x1 * c - x2 * sn;
        k[base + 1] = x1 * sn + x2 * c;
    }
}

// ---------------------------------------------------------------------------
// Sliding-window flash attention, fp32.
// Block = (q-tile of 128, head). 256 threads as 16x16 grid.
// Each thread: 8 score rows x 8 score cols (4+4 split); O accum 8 rows x 4 d.
// smem: Qt[64][128], Kt[64][128], Vs[128][64], Ps[128][128] = 160 KB dynamic.
// ---------------------------------------------------------------------------
__global__ __launch_bounds__(256, 1) void attn_kernel(
    const float* __restrict__ q, const float* __restrict__ k,
    const float* __restrict__ v, float* __restrict__ o)
{
    extern __shared__ float sm[];
    float* Qt = sm;               // [d][r]  64*128
    float* Kt = sm + 8192;        // [d][c]  64*128
    float* Vs = sm + 16384;       // [c][d]  128*64
    float* Ps = sm + 24576;       // [r][c]  128*128

    const int t  = threadIdx.x;
    const int tx = t & 15;
    const int ty = t >> 4;
    const int h  = blockIdx.y;
    const int qs = blockIdx.x * 128;

    // Load Q tile transposed: Qt[d][r] = q[(qs+r)*DIM + h*HD + d]
#pragma unroll
    for (int i = 0; i < 8; i++) {
        int f  = i * 256 + t;       // float4 id; consecutive t -> coalesced
        int r  = f >> 4;
        int c4 = (f & 15) * 4;
        float4 vq = *(const float4*)(q + (size_t)(qs + r) * DIM + h * HD + c4);
        Qt[(c4 + 0) * 128 + r] = vq.x;
        Qt[(c4 + 1) * 128 + r] = vq.y;
        Qt[(c4 + 2) * 128 + r] = vq.z;
        Qt[(c4 + 3) * 128 + r] = vq.w;
    }

    float m[8], l[8], acc[8][4];
    int r_of[8], c_of[8];
#pragma unroll
    for (int i = 0; i < 8; i++) {
        m[i] = -1e30f; l[i] = 0.0f;
        acc[i][0] = acc[i][1] = acc[i][2] = acc[i][3] = 0.0f;
        r_of[i] = ty * 4 + (i & 3) + ((i >> 2) << 6);
        c_of[i] = tx * 4 + (i & 3) + ((i >> 2) << 6);
    }

    int kt0 = qs - WIN;
    if (kt0 < 0) kt0 = 0;

    for (int kt = kt0; kt <= qs; kt += 128) {
        __syncthreads();   // previous phase-B reads done before overwrite
        // Load K (transposed) + V (natural)
#pragma unroll
        for (int i = 0; i < 8; i++) {
            int f  = i * 256 + t;
            int r  = f >> 4;
            int c4 = (f & 15) * 4;
            float4 kv = *(const float4*)(k + (size_t)(kt + r) * DIM + h * HD + c4);
            Kt[(c4 + 0) * 128 + r] = kv.x;
            Kt[(c4 + 1) * 128 + r] = kv.y;
            Kt[(c4 + 2) * 128 + r] = kv.z;
            Kt[(c4 + 3) * 128 + r] = kv.w;
            float4 vv = *(const float4*)(v + (size_t)(kt + r) * DIM + h * HD + c4);
            *(float4*)&Vs[r * 64 + c4] = vv;
        }
        __syncthreads();

        // Phase A: S = Q K^T
        float sc[8][8];
#pragma unroll
        for (int i = 0; i < 8; i++)
#pragma unroll
            for (int j = 0; j < 8; j++) sc[i][j] = 0.0f;

#pragma unroll 4
        for (int d = 0; d < 64; d++) {
            float4 a0 = *(const float4*)&Qt[d * 128 + ty * 4];
            float4 a1 = *(const float4*)&Qt[d * 128 + 64 + ty * 4];
            float4 b0 = *(const float4*)&Kt[d * 128 + tx * 4];
            float4 b1 = *(const float4*)&Kt[d * 128 + 64 + tx * 4];
            float a[8] = {a0.x, a0.y, a0.z, a0.w, a1.x, a1.y, a1.z, a1.w};
            float b[8] = {b0.x, b0.y, b0.z, b0.w, b1.x, b1.y, b1.z, b1.w};
#pragma unroll
            for (int i = 0; i < 8; i++)
#pragma unroll
                for (int j = 0; j < 8; j++)
                    sc[i][j] = fmaf(a[i], b[j], sc[i][j]);
        }

        // Mask + online softmax (row stats reduced over the 16 tx lanes)
#pragma unroll
        for (int i = 0; i < 8; i++) {
            int qg = qs + r_of[i];
            float rowm = m[i];
#pragma unroll
            for (int j = 0; j < 8; j++) {
                int kg = kt + c_of[j];
                bool valid = (kg <= qg) && (kg > qg - WIN);
                float sv = valid ? sc[i][j] * 0.125f : -1e30f;
                sc[i][j] = sv;
                rowm = fmaxf(rowm, sv);
            }
#pragma unroll
            for (int off = 1; off < 16; off <<= 1)
                rowm = fmaxf(rowm, __shfl_xor_sync(0xffffffffu, rowm, off));

            float alpha = __expf(m[i] - rowm);
            float rs = 0.0f;
#pragma unroll
            for (int j = 0; j < 8; j++) {
                float p = (sc[i][j] > -1e29f) ? __expf(sc[i][j] - rowm) : 0.0f;
                sc[i][j] = p;
                rs += p;
            }
#pragma unroll
            for (int off = 1; off < 16; off <<= 1)
                rs += __shfl_xor_sync(0xffffffffu, rs, off);

            m[i] = rowm;
            l[i] = l[i] * alpha + rs;
            acc[i][0] *= alpha; acc[i][1] *= alpha;
            acc[i][2] *= alpha; acc[i][3] *= alpha;

            *(float4*)&Ps[r_of[i] * 128 + tx * 4] =
                make_float4(sc[i][0], sc[i][1], sc[i][2], sc[i][3]);
            *(float4*)&Ps[r_of[i] * 128 + 64 + tx * 4] =
                make_float4(sc[i][4], sc[i][5], sc[i][6], sc[i][7]);
        }
        __syncthreads();

        // Phase B: O += P V
        for (int kk = 0; kk < 128; kk += 4) {
            float4 vv0 = *(const float4*)&Vs[(kk + 0) * 64 + tx * 4];
            float4 vv1 = *(const float4*)&Vs[(kk + 1) * 64 + tx * 4];
            float4 vv2 = *(const float4*)&Vs[(kk + 2) * 64 + tx * 4];
            float4 vv3 = *(const float4*)&Vs[(kk + 3) * 64 + tx * 4];
#pragma unroll
            for (int i = 0; i < 8; i++) {
                float4 pp = *(const float4*)&Ps[r_of[i] * 128 + kk];
                acc[i][0] = fmaf(pp.x, vv0.x, acc[i][0]);
                acc[i][1] = fmaf(pp.x, vv0.y, acc[i][1]);
                acc[i][2] = fmaf(pp.x, vv0.z, acc[i][2]);
                acc[i][3] = fmaf(pp.x, vv0.w, acc[i][3]);
                acc[i][0] = fmaf(pp.y, vv1.x, acc[i][0]);
                acc[i][1] = fmaf(pp.y, vv1.y, acc[i][1]);
                acc[i][2] = fmaf(pp.y, vv1.z, acc[i][2]);
                acc[i][3] = fmaf(pp.y, vv1.w, acc[i][3]);
                acc[i][0] = fmaf(pp.z, vv2.x, acc[i][0]);
                acc[i][1] = fmaf(pp.z, vv2.y, acc[i][1]);
                acc[i][2] = fmaf(pp.z, vv2.z, acc[i][2]);
                acc[i][3] = fmaf(pp.z, vv2.w, acc[i][3]);
                acc[i][0] = fmaf(pp.w, vv3.x, acc[i][0]);
                acc[i][1] = fmaf(pp.w, vv3.y, acc[i][1]);
                acc[i][2] = fmaf(pp.w, vv3.z, acc[i][2]);
                acc[i][3] = fmaf(pp.w, vv3.w, acc[i][3]);
            }
        }
    }

    // Epilogue: normalize and write O (thread owns d-cols tx*4..tx*4+3)
#pragma unroll
    for (int i = 0; i < 8; i++) {
        float inv = 1.0f / l[i];
        float4 ov = make_float4(acc[i][0] * inv, acc[i][1] * inv,
                                acc[i][2] * inv, acc[i][3] * inv);
        *(float4*)(o + (size_t)(qs + r_of[i]) * DIM + h * HD + tx * 4) = ov;
    }
}

// ---------------------------------------------------------------------------
extern "C" void kernel_launch(void* const* d_in, const int* in_sizes, int n_in,
                              void* d_out, int out_size)
{
    const float* x  = (const float*)d_in[0];
    const float* Wq = (const float*)d_in[1];
    const float* Wk = (const float*)d_in[2];
    const float* Wv = (const float*)d_in[3];
    const float* Wo = (const float*)d_in[4];
    float* out = (float*)d_out;

    float *q, *k, *v, *o;
    cudaGetSymbolAddress((void**)&q, g_q);
    cudaGetSymbolAddress((void**)&k, g_k);
    cudaGetSymbolAddress((void**)&v, g_v);
    cudaGetSymbolAddress((void**)&o, g_o);

    const int attn_smem = 40960 * sizeof(float);  // 160 KB
    cudaFuncSetAttribute(attn_kernel,
                         cudaFuncAttributeMaxDynamicSharedMemorySize, attn_smem);

    // 1) Fused Q/K/V projections
    dim3 g1(DIM / 128, S_LEN / 128, 3);
    sgemm_nt<3><<<g1, 256>>>(x, Wq, Wk, Wv, q, k, v, S_LEN, DIM, DIM);

    // 2) RoPE on q and k (in place)
    int rope_n = S_LEN * NH * (HD / 2);
    rope_kernel<<<(rope_n + 255) / 256, 256>>>(q, k);

    // 3) Sliding-window attention
    attn_kernel<<<dim3(S_LEN / 128, NH), 256, attn_smem>>>(q, k, v, o);

    // 4) Output projection
    dim3 g2(DIM / 128, S_LEN / 128, 1);
    sgemm_nt<1><<<g2, 256>>>(o, Wo, Wo, Wo, out, out, out, S_LEN, DIM, DIM);
}

// round 6
// speedup vs baseline: 1.6378x; 1.6378x over previous
#include <cuda_runtime.h>
#include <cuda_bf16.h>
#include <math.h>
#include <cstdint>

#define S_LEN 8192
#define DIM   1024
#define NH    16
#define HD    64
#define WIN   512

// ---------------- scratch (allocation-free rule: device globals) ----------
__device__ __align__(256) float g_q[S_LEN * DIM];
__device__ __align__(256) float g_k[S_LEN * DIM];
__device__ __align__(256) float g_v[S_LEN * DIM];
__device__ __align__(256) float g_o[S_LEN * DIM];
__device__ __align__(256) __nv_bfloat16 g_xhi[S_LEN * DIM];
__device__ __align__(256) __nv_bfloat16 g_xlo[S_LEN * DIM];
__device__ __align__(256) __nv_bfloat16 g_whi[4 * DIM * DIM];
__device__ __align__(256) __nv_bfloat16 g_wlo[4 * DIM * DIM];
__device__ __align__(256) __nv_bfloat16 g_ohi[S_LEN * DIM];
__device__ __align__(256) __nv_bfloat16 g_olo[S_LEN * DIM];

// ---------------- fp32 -> bf16 hi/lo split --------------------------------
__global__ void split2_kernel(const float* __restrict__ src,
                              __nv_bfloat16* __restrict__ hi,
                              __nv_bfloat16* __restrict__ lo, int n4)
{
    int i = blockIdx.x * blockDim.x + threadIdx.x;
    if (i >= n4) return;
    float4 x = ((const float4*)src)[i];
    __nv_bfloat16 h0 = __float2bfloat16(x.x);
    __nv_bfloat16 h1 = __float2bfloat16(x.y);
    __nv_bfloat16 h2 = __float2bfloat16(x.z);
    __nv_bfloat16 h3 = __float2bfloat16(x.w);
    __nv_bfloat16 l0 = __float2bfloat16(x.x - __bfloat162float(h0));
    __nv_bfloat16 l1 = __float2bfloat16(x.y - __bfloat162float(h1));
    __nv_bfloat16 l2 = __float2bfloat16(x.z - __bfloat162float(h2));
    __nv_bfloat16 l3 = __float2bfloat16(x.w - __bfloat162float(h3));
    uint2 uh, ul;
    uh.x = (uint32_t)__bfloat16_as_ushort(h0) | ((uint32_t)__bfloat16_as_ushort(h1) << 16);
    uh.y = (uint32_t)__bfloat16_as_ushort(h2) | ((uint32_t)__bfloat16_as_ushort(h3) << 16);
    ul.x = (uint32_t)__bfloat16_as_ushort(l0) | ((uint32_t)__bfloat16_as_ushort(l1) << 16);
    ul.y = (uint32_t)__bfloat16_as_ushort(l2) | ((uint32_t)__bfloat16_as_ushort(l3) << 16);
    ((uint2*)hi)[i] = uh;
    ((uint2*)lo)[i] = ul;
}

// ---------------- HMMA helpers --------------------------------------------
__device__ __forceinline__ uint32_t smem_u32(const void* p) {
    uint32_t a;
    asm("{ .reg .u64 t; cvta.to.shared.u64 t, %1; cvt.u32.u64 %0, t; }"
        : "=r"(a) : "l"(p));
    return a;
}
__device__ __forceinline__ void ldsm_x4(uint32_t* r, uint32_t saddr) {
    asm volatile("ldmatrix.sync.aligned.m8n8.x4.shared.b16 {%0,%1,%2,%3}, [%4];"
                 : "=r"(r[0]), "=r"(r[1]), "=r"(r[2]), "=r"(r[3]) : "r"(saddr));
}
__device__ __forceinline__ void mma_bf16(float* c, const uint32_t* a,
                                         uint32_t b0, uint32_t b1) {
    asm volatile(
        "mma.sync.aligned.m16n8k16.row.col.f32.bf16.bf16.f32 "
        "{%0,%1,%2,%3}, {%4,%5,%6,%7}, {%8,%9}, {%0,%1,%2,%3};"
        : "+f"(c[0]), "+f"(c[1]), "+f"(c[2]), "+f"(c[3])
        : "r"(a[0]), "r"(a[1]), "r"(a[2]), "r"(a[3]), "r"(b0), "r"(b1));
}
#define CP_ASYNC16(saddr, gptr) \
    asm volatile("cp.async.ca.shared.global [%0], [%1], 16;" \
                 :: "r"(saddr), "l"(gptr))
#define CP_COMMIT()  asm volatile("cp.async.commit_group;" ::: "memory")
#define CP_WAIT(n)   asm volatile("cp.async.wait_group %0;" :: "n"(n) : "memory")

// ---------------- HMMA split-fp32 GEMM NT ----------------------------------
// C[M,N] = A[M,K]*B[N,K]^T, A/B pre-split into bf16 hi/lo. fp32 accum.
// CTA: 128x128 tile, 256 thr (8 warps, warp tile 64x32). BK=32.
// smem rows padded to 40 bf16 (80B stride) -> conflict-free ldmatrix.
// 2-stage cp.async pipeline. grid.z fuses QKV.
#define SKB   40
#define TILEB (128 * SKB * 2)            // 10240 B per tile
#define STAGEB (4 * TILEB)               // 40960 B per stage
#define GEMM_SMEM (2 * STAGEB)           // 81920 B
#define NCHUNK (DIM / 32)

__global__ __launch_bounds__(256)
void gemm_hmma(const __nv_bfloat16* __restrict__ Ahi,
               const __nv_bfloat16* __restrict__ Alo,
               const __nv_bfloat16* __restrict__ Bhi_all,
               const __nv_bfloat16* __restrict__ Blo_all,
               float* __restrict__ C0, float* __restrict__ C1,
               float* __restrict__ C2)
{
    extern __shared__ char smem[];
    const uint32_t sb = smem_u32(smem);
    const int t    = threadIdx.x;
    const int wid  = t >> 5;
    const int lane = t & 31;
    const int bm = blockIdx.y * 128;
    const int bn = blockIdx.x * 128;
    const int z  = blockIdx.z;
    const __nv_bfloat16* bhi = Bhi_all + (size_t)z * DIM * DIM;
    const __nv_bfloat16* blo = Blo_all + (size_t)z * DIM * DIM;
    float* C = (z == 0) ? C0 : (z == 1 ? C1 : C2);

    const int wm = (wid >> 2) * 64;      // warp row offset in tile
    const int wn = (wid & 3) * 32;       // warp col offset in tile

    float acc[4][4][4];
#pragma unroll
    for (int i = 0; i < 4; i++)
#pragma unroll
        for (int j = 0; j < 4; j++)
#pragma unroll
            for (int r = 0; r < 4; r++) acc[i][j][r] = 0.0f;

    // cp.async issue helper mapping: 8 copies of 16B per thread per chunk
    // id = t + 256*i ; tile = id>>9 (0=Ahi,1=Alo,2=Bhi,3=Blo); w=id&511;
    // row = w>>2; colgrp = (w&3)*8
    auto issue_chunk = [&](int kc, int stage) {
        const uint32_t sbase = sb + stage * STAGEB;
#pragma unroll
        for (int i = 0; i < 8; i++) {
            int id   = t + 256 * i;
            int tile = id >> 9;
            int w    = id & 511;
            int row  = w >> 2;
            int cg   = (w & 3) * 8;
            uint32_t so = sbase + tile * TILEB + (uint32_t)(row * SKB + cg) * 2;
            const __nv_bfloat16* gp;
            if (tile == 0)      gp = Ahi + (size_t)(bm + row) * DIM + kc + cg;
            else if (tile == 1) gp = Alo + (size_t)(bm + row) * DIM + kc + cg;
            else if (tile == 2) gp = bhi + (size_t)(bn + row) * DIM + kc + cg;
            else                gp = blo + (size_t)(bn + row) * DIM + kc + cg;
            CP_ASYNC16(so, gp);
        }
        CP_COMMIT();
    };

    issue_chunk(0, 0);

    const int lrow = lane & 7;
    const int seg  = lane >> 3;

    for (int c = 0; c < NCHUNK; c++) {
        CP_WAIT(0);
        __syncthreads();
        if (c + 1 < NCHUNK) issue_chunk((c + 1) * 32, (c + 1) & 1);

        const uint32_t stg = sb + (c & 1) * STAGEB;
#pragma unroll
        for (int ks = 0; ks < 32; ks += 16) {
            // B fragments: 2 pairs (4 n-tiles), hi and lo
            uint32_t bh[2][4], bl[2][4];
#pragma unroll
            for (int p = 0; p < 2; p++) {
                int br = wn + p * 16 + (seg >> 1) * 8 + lrow;
                int bc = ks + (seg & 1) * 8;
                uint32_t off = (uint32_t)(br * SKB + bc) * 2;
                ldsm_x4(bh[p], stg + 2 * TILEB + off);
                ldsm_x4(bl[p], stg + 3 * TILEB + off);
            }
            // A fragments per m-tile (hi then lo, reuse regs)
#pragma unroll
            for (int mt = 0; mt < 4; mt++) {
                int ar = wm + mt * 16 + (seg & 1) * 8 + lrow;
                int ac = ks + (seg >> 1) * 8;
                uint32_t off = (uint32_t)(ar * SKB + ac) * 2;
                uint32_t ah[4], al[4];
                ldsm_x4(ah, stg + 0 * TILEB + off);
                ldsm_x4(al, stg + 1 * TILEB + off);
#pragma unroll
                for (int nt = 0; nt < 4; nt++) {
                    int p = nt >> 1, q = (nt & 1) * 2;
                    mma_bf16(acc[mt][nt], ah, bh[p][q], bh[p][q + 1]);
                    mma_bf16(acc[mt][nt], ah, bl[p][q], bl[p][q + 1]);
                    mma_bf16(acc[mt][nt], al, bh[p][q], bh[p][q + 1]);
                }
            }
        }
        __syncthreads();
    }

    // Epilogue: fragment layout c0,c1 -> row lane/4, cols (lane%4)*2(+1);
    // c2,c3 -> row lane/4+8
    const int trow = lane >> 2;
    const int tcol = (lane & 3) * 2;
#pragma unroll
    for (int mt = 0; mt < 4; mt++) {
#pragma unroll
        for (int nt = 0; nt < 4; nt++) {
            size_t r0 = (size_t)(bm + wm + mt * 16 + trow);
            size_t cc = (size_t)(bn + wn + nt * 8 + tcol);
            *(float2*)(C + r0 * DIM + cc) =
                make_float2(acc[mt][nt][0], acc[mt][nt][1]);
            *(float2*)(C + (r0 + 8) * DIM + cc) =
                make_float2(acc[mt][nt][2], acc[mt][nt][3]);
        }
    }
}

// ---------------- RoPE (unchanged, validated) ------------------------------
__global__ void rope_kernel(float* __restrict__ q, float* __restrict__ k)
{
    int idx = blockIdx.x * blockDim.x + threadIdx.x;
    if (idx >= S_LEN * NH * (HD / 2)) return;
    int j = idx & 31;
    int h = (idx >> 5) & 15;
    int s = idx >> 9;

    float inv_freq = 1.0f / powf(10000.0f, (float)(2 * j) * (1.0f / 64.0f));
    float ang = (float)s * inv_freq;
    float c = cosf(ang), sn = sinf(ang);

    int base = s * DIM + h * HD + 2 * j;
    {
        float x1 = q[base], x2 = q[base + 1];
        q[base]     = x1 * c - x2 * sn;
        q[base + 1] = x1 * sn + x2 * c;
    }
    {
        float x1 = k[base], x2 = k[base + 1];
        k[base]     = x1 * c - x2 * sn;
        k[base + 1] = x1 * sn + x2 * c;
    }
}

// ---------------- sliding-window flash attention (unchanged, validated) ----
__global__ __launch_bounds__(256, 1) void attn_kernel(
    const float* __restrict__ q, const float* __restrict__ k,
    const float* __restrict__ v, float* __restrict__ o)
{
    extern __shared__ float sm[];
    float* Qt = sm;               // [d][r]  64*128
    float* Kt = sm + 8192;        // [d][c]  64*128
    float* Vs = sm + 16384;       // [c][d]  128*64
    float* Ps = sm + 24576;       // [r][c]  128*128

    const int t  = threadIdx.x;
    const int tx = t & 15;
    const int ty = t >> 4;
    const int h  = blockIdx.y;
    const int qs = blockIdx.x * 128;

#pragma unroll
    for (int i = 0; i < 8; i++) {
        int f  = i * 256 + t;
        int r  = f >> 4;
        int c4 = (f & 15) * 4;
        float4 vq = *(const float4*)(q + (size_t)(qs + r) * DIM + h * HD + c4);
        Qt[(c4 + 0) * 128 + r] = vq.x;
        Qt[(c4 + 1) * 128 + r] = vq.y;
        Qt[(c4 + 2) * 128 + r] = vq.z;
        Qt[(c4 + 3) * 128 + r] = vq.w;
    }

    float m[8], l[8], acc[8][4];
    int r_of[8], c_of[8];
#pragma unroll
    for (int i = 0; i < 8; i++) {
        m[i] = -1e30f; l[i] = 0.0f;
        acc[i][0] = acc[i][1] = acc[i][2] = acc[i][3] = 0.0f;
        r_of[i] = ty * 4 + (i & 3) + ((i >> 2) << 6);
        c_of[i] = tx * 4 + (i & 3) + ((i >> 2) << 6);
    }

    int kt0 = qs - WIN;
    if (kt0 < 0) kt0 = 0;

    for (int kt = kt0; kt <= qs; kt += 128) {
        __syncthreads();
#pragma unroll
        for (int i = 0; i < 8; i++) {
            int f  = i * 256 + t;
            int r  = f >> 4;
            int c4 = (f & 15) * 4;
            float4 kv = *(const float4*)(k + (size_t)(kt + r) * DIM + h * HD + c4);
            Kt[(c4 + 0) * 128 + r] = kv.x;
            Kt[(c4 + 1) * 128 + r] = kv.y;
            Kt[(c4 + 2) * 128 + r] = kv.z;
            Kt[(c4 + 3) * 128 + r] = kv.w;
            float4 vv = *(const float4*)(v + (size_t)(kt + r) * DIM + h * HD + c4);
            *(float4*)&Vs[r * 64 + c4] = vv;
        }
        __syncthreads();

        float sc[8][8];
#pragma unroll
        for (int i = 0; i < 8; i++)
#pragma unroll
            for (int j = 0; j < 8; j++) sc[i][j] = 0.0f;

#pragma unroll 4
        for (int d = 0; d < 64; d++) {
            float4 a0 = *(const float4*)&Qt[d * 128 + ty * 4];
            float4 a1 = *(const float4*)&Qt[d * 128 + 64 + ty * 4];
            float4 b0 = *(const float4*)&Kt[d * 128 + tx * 4];
            float4 b1 = *(const float4*)&Kt[d * 128 + 64 + tx * 4];
            float a[8] = {a0.x, a0.y, a0.z, a0.w, a1.x, a1.y, a1.z, a1.w};
            float b[8] = {b0.x, b0.y, b0.z, b0.w, b1.x, b1.y, b1.z, b1.w};
#pragma unroll
            for (int i = 0; i < 8; i++)
#pragma unroll
                for (int j = 0; j < 8; j++)
                    sc[i][j] = fmaf(a[i], b[j], sc[i][j]);
        }

#pragma unroll
        for (int i = 0; i < 8; i++) {
            int qg = qs + r_of[i];
            float rowm = m[i];
#pragma unroll
            for (int j = 0; j < 8; j++) {
                int kg = kt + c_of[j];
                bool valid = (kg <= qg) && (kg > qg - WIN);
                float sv = valid ? sc[i][j] * 0.125f : -1e30f;
                sc[i][j] = sv;
                rowm = fmaxf(rowm, sv);
            }
#pragma unroll
            for (int off = 1; off < 16; off <<= 1)
                rowm = fmaxf(rowm, __shfl_xor_sync(0xffffffffu, rowm, off));

            float alpha = __expf(m[i] - rowm);
            float rs = 0.0f;
#pragma unroll
            for (int j = 0; j < 8; j++) {
                float p = (sc[i][j] > -1e29f) ? __expf(sc[i][j] - rowm) : 0.0f;
                sc[i][j] = p;
                rs += p;
            }
#pragma unroll
            for (int off = 1; off < 16; off <<= 1)
                rs += __shfl_xor_sync(0xffffffffu, rs, off);

            m[i] = rowm;
            l[i] = l[i] * alpha + rs;
            acc[i][0] *= alpha; acc[i][1] *= alpha;
            acc[i][2] *= alpha; acc[i][3] *= alpha;

            *(float4*)&Ps[r_of[i] * 128 + tx * 4] =
                make_float4(sc[i][0], sc[i][1], sc[i][2], sc[i][3]);
            *(float4*)&Ps[r_of[i] * 128 + 64 + tx * 4] =
                make_float4(sc[i][4], sc[i][5], sc[i][6], sc[i][7]);
        }
        __syncthreads();

        for (int kk = 0; kk < 128; kk += 4) {
            float4 vv0 = *(const float4*)&Vs[(kk + 0) * 64 + tx * 4];
            float4 vv1 = *(const float4*)&Vs[(kk + 1) * 64 + tx * 4];
            float4 vv2 = *(const float4*)&Vs[(kk + 2) * 64 + tx * 4];
            float4 vv3 = *(const float4*)&Vs[(kk + 3) * 64 + tx * 4];
#pragma unroll
            for (int i = 0; i < 8; i++) {
                float4 pp = *(const float4*)&Ps[r_of[i] * 128 + kk];
                acc[i][0] = fmaf(pp.x, vv0.x, acc[i][0]);
                acc[i][1] = fmaf(pp.x, vv0.y, acc[i][1]);
                acc[i][2] = fmaf(pp.x, vv0.z, acc[i][2]);
                acc[i][3] = fmaf(pp.x, vv0.w, acc[i][3]);
                acc[i][0] = fmaf(pp.y, vv1.x, acc[i][0]);
                acc[i][1] = fmaf(pp.y, vv1.y, acc[i][1]);
                acc[i][2] = fmaf(pp.y, vv1.z, acc[i][2]);
                acc[i][3] = fmaf(pp.y, vv1.w, acc[i][3]);
                acc[i][0] = fmaf(pp.z, vv2.x, acc[i][0]);
                acc[i][1] = fmaf(pp.z, vv2.y, acc[i][1]);
                acc[i][2] = fmaf(pp.z, vv2.z, acc[i][2]);
                acc[i][3] = fmaf(pp.z, vv2.w, acc[i][3]);
                acc[i][0] = fmaf(pp.w, vv3.x, acc[i][0]);
                acc[i][1] = fmaf(pp.w, vv3.y, acc[i][1]);
                acc[i][2] = fmaf(pp.w, vv3.z, acc[i][2]);
                acc[i][3] = fmaf(pp.w, vv3.w, acc[i][3]);
            }
        }
    }

#pragma unroll
    for (int i = 0; i < 8; i++) {
        float inv = 1.0f / l[i];
        float4 ov = make_float4(acc[i][0] * inv, acc[i][1] * inv,
                                acc[i][2] * inv, acc[i][3] * inv);
        *(float4*)(o + (size_t)(qs + r_of[i]) * DIM + h * HD + tx * 4) = ov;
    }
}

// ---------------------------------------------------------------------------
extern "C" void kernel_launch(void* const* d_in, const int* in_sizes, int n_in,
                              void* d_out, int out_size)
{
    const float* x  = (const float*)d_in[0];
    const float* Wq = (const float*)d_in[1];
    const float* Wk = (const float*)d_in[2];
    const float* Wv = (const float*)d_in[3];
    const float* Wo = (const float*)d_in[4];
    float* out = (float*)d_out;

    float *q, *k, *v, *o;
    __nv_bfloat16 *xhi, *xlo, *whi, *wlo, *ohi, *olo;
    cudaGetSymbolAddress((void**)&q, g_q);
    cudaGetSymbolAddress((void**)&k, g_k);
    cudaGetSymbolAddress((void**)&v, g_v);
    cudaGetSymbolAddress((void**)&o, g_o);
    cudaGetSymbolAddress((void**)&xhi, g_xhi);
    cudaGetSymbolAddress((void**)&xlo, g_xlo);
    cudaGetSymbolAddress((void**)&whi, g_whi);
    cudaGetSymbolAddress((void**)&wlo, g_wlo);
    cudaGetSymbolAddress((void**)&ohi, g_ohi);
    cudaGetSymbolAddress((void**)&olo, g_olo);

    const int attn_smem = 40960 * sizeof(float);  // 160 KB
    cudaFuncSetAttribute(attn_kernel,
                         cudaFuncAttributeMaxDynamicSharedMemorySize, attn_smem);
    cudaFuncSetAttribute(gemm_hmma,
                         cudaFuncAttributeMaxDynamicSharedMemorySize, GEMM_SMEM);

    // 1) Split x and weights into bf16 hi/lo
    {
        int n4 = S_LEN * DIM / 4;
        split2_kernel<<<(n4 + 255) / 256, 256>>>(x, xhi, xlo, n4);
        int w4 = DIM * DIM / 4;
        split2_kernel<<<(w4 + 255) / 256, 256>>>(Wq, whi + 0 * DIM * DIM, wlo + 0 * DIM * DIM, w4);
        split2_kernel<<<(w4 + 255) / 256, 256>>>(Wk, whi + 1 * DIM * DIM, wlo + 1 * DIM * DIM, w4);
        split2_kernel<<<(w4 + 255) / 256, 256>>>(Wv, whi + 2 * DIM * DIM, wlo + 2 * DIM * DIM, w4);
        split2_kernel<<<(w4 + 255) / 256, 256>>>(Wo, whi + 3 * DIM * DIM, wlo + 3 * DIM * DIM, w4);
    }

    // 2) Fused Q/K/V projections (HMMA split-fp32)
    gemm_hmma<<<dim3(DIM / 128, S_LEN / 128, 3), 256, GEMM_SMEM>>>(
        xhi, xlo, whi, wlo, q, k, v);

    // 3) RoPE on q and k (in place)
    int rope_n = S_LEN * NH * (HD / 2);
    rope_kernel<<<(rope_n + 255) / 256, 256>>>(q, k);

    // 4) Sliding-window attention (fp32)
    attn_kernel<<<dim3(S_LEN / 128, NH), 256, attn_smem>>>(q, k, v, o);

    // 5) Split attention output, then output projection (HMMA split-fp32)
    {
        int n4 = S_LEN * DIM / 4;
        split2_kernel<<<(n4 + 255) / 256, 256>>>(o, ohi, olo, n4);
    }
    gemm_hmma<<<dim3(DIM / 128, S_LEN / 128, 1), 256, GEMM_SMEM>>>(
        ohi, olo, whi + 3 * DIM * DIM, wlo + 3 * DIM * DIM, out, out, out);
}

// round 8
// speedup vs baseline: 2.2537x; 1.3761x over previous
#include <cuda_runtime.h>
#include <cuda_bf16.h>
#include <math.h>
#include <cstdint>

#define S_LEN 8192
#define DIM   1024
#define NH    16
#define HD    64
#define WIN   512

// ---------------- scratch (allocation-free rule: device globals) ----------
__device__ __align__(256) float g_q[S_LEN * DIM];
__device__ __align__(256) float g_k[S_LEN * DIM];
__device__ __align__(256) float g_v[S_LEN * DIM];
__device__ __align__(256) float g_o[S_LEN * DIM];
__device__ __align__(256) __nv_bfloat16 g_xhi[S_LEN * DIM];
__device__ __align__(256) __nv_bfloat16 g_xlo[S_LEN * DIM];
__device__ __align__(256) __nv_bfloat16 g_whi[4 * DIM * DIM];
__device__ __align__(256) __nv_bfloat16 g_wlo[4 * DIM * DIM];
__device__ __align__(256) __nv_bfloat16 g_ohi[S_LEN * DIM];
__device__ __align__(256) __nv_bfloat16 g_olo[S_LEN * DIM];
__device__ __align__(256) __nv_bfloat16 g_qhi[S_LEN * DIM];
__device__ __align__(256) __nv_bfloat16 g_qlo[S_LEN * DIM];
__device__ __align__(256) __nv_bfloat16 g_khi[S_LEN * DIM];
__device__ __align__(256) __nv_bfloat16 g_klo[S_LEN * DIM];
__device__ __align__(256) __nv_bfloat16 g_vhi[S_LEN * DIM];
__device__ __align__(256) __nv_bfloat16 g_vlo[S_LEN * DIM];

// ---------------- fp32 -> bf16 hi/lo split --------------------------------
__global__ void split2_kernel(const float* __restrict__ src,
                              __nv_bfloat16* __restrict__ hi,
                              __nv_bfloat16* __restrict__ lo, int n4)
{
    int i = blockIdx.x * blockDim.x + threadIdx.x;
    if (i >= n4) return;
    float4 x = ((const float4*)src)[i];
    __nv_bfloat16 h0 = __float2bfloat16(x.x);
    __nv_bfloat16 h1 = __float2bfloat16(x.y);
    __nv_bfloat16 h2 = __float2bfloat16(x.z);
    __nv_bfloat16 h3 = __float2bfloat16(x.w);
    __nv_bfloat16 l0 = __float2bfloat16(x.x - __bfloat162float(h0));
    __nv_bfloat16 l1 = __float2bfloat16(x.y - __bfloat162float(h1));
    __nv_bfloat16 l2 = __float2bfloat16(x.z - __bfloat162float(h2));
    __nv_bfloat16 l3 = __float2bfloat16(x.w - __bfloat162float(h3));
    uint2 uh, ul;
    uh.x = (uint32_t)__bfloat16_as_ushort(h0) | ((uint32_t)__bfloat16_as_ushort(h1) << 16);
    uh.y = (uint32_t)__bfloat16_as_ushort(h2) | ((uint32_t)__bfloat16_as_ushort(h3) << 16);
    ul.x = (uint32_t)__bfloat16_as_ushort(l0) | ((uint32_t)__bfloat16_as_ushort(l1) << 16);
    ul.y = (uint32_t)__bfloat16_as_ushort(l2) | ((uint32_t)__bfloat16_as_ushort(l3) << 16);
    ((uint2*)hi)[i] = uh;
    ((uint2*)lo)[i] = ul;
}

// ---------------- HMMA helpers --------------------------------------------
__device__ __forceinline__ uint32_t smem_u32(const void* p) {
    uint32_t a;
    asm("{ .reg .u64 t; cvta.to.shared.u64 t, %1; cvt.u32.u64 %0, t; }"
        : "=r"(a) : "l"(p));
    return a;
}
__device__ __forceinline__ void ldsm_x4(uint32_t* r, uint32_t saddr) {
    asm volatile("ldmatrix.sync.aligned.m8n8.x4.shared.b16 {%0,%1,%2,%3}, [%4];"
                 : "=r"(r[0]), "=r"(r[1]), "=r"(r[2]), "=r"(r[3]) : "r"(saddr));
}
__device__ __forceinline__ void ldsm_x4_trans(uint32_t* r, uint32_t saddr) {
    asm volatile("ldmatrix.sync.aligned.m8n8.x4.trans.shared.b16 {%0,%1,%2,%3}, [%4];"
                 : "=r"(r[0]), "=r"(r[1]), "=r"(r[2]), "=r"(r[3]) : "r"(saddr));
}
__device__ __forceinline__ void mma_bf16(float* c, const uint32_t* a,
                                         uint32_t b0, uint32_t b1) {
    asm volatile(
        "mma.sync.aligned.m16n8k16.row.col.f32.bf16.bf16.f32 "
        "{%0,%1,%2,%3}, {%4,%5,%6,%7}, {%8,%9}, {%0,%1,%2,%3};"
        : "+f"(c[0]), "+f"(c[1]), "+f"(c[2]), "+f"(c[3])
        : "r"(a[0]), "r"(a[1]), "r"(a[2]), "r"(a[3]), "r"(b0), "r"(b1));
}
#define CP_ASYNC16(saddr, gptr) \
    asm volatile("cp.async.ca.shared.global [%0], [%1], 16;" \
                 :: "r"(saddr), "l"(gptr))
#define CP_COMMIT()  asm volatile("cp.async.commit_group;" ::: "memory")
#define CP_WAIT(n)   asm volatile("cp.async.wait_group %0;" :: "n"(n) : "memory")

// pack two floats -> bf16x2 (x in low/k, y in high/k+1)
__device__ __forceinline__ uint32_t pack_bf2(float x, float y) {
    __nv_bfloat16 bx = __float2bfloat16(x), by = __float2bfloat16(y);
    return (uint32_t)__bfloat16_as_ushort(bx) |
           ((uint32_t)__bfloat16_as_ushort(by) << 16);
}

// ---------------- HMMA split-fp32 GEMM NT (validated R6) -------------------
#define SKB   40
#define TILEB (128 * SKB * 2)
#define STAGEB (4 * TILEB)
#define GEMM_SMEM (2 * STAGEB)
#define NCHUNK (DIM / 32)

__global__ __launch_bounds__(256)
void gemm_hmma(const __nv_bfloat16* __restrict__ Ahi,
               const __nv_bfloat16* __restrict__ Alo,
               const __nv_bfloat16* __restrict__ Bhi_all,
               const __nv_bfloat16* __restrict__ Blo_all,
               float* __restrict__ C0, float* __restrict__ C1,
               float* __restrict__ C2)
{
    extern __shared__ char smem[];
    const uint32_t sb = smem_u32(smem);
    const int t    = threadIdx.x;
    const int wid  = t >> 5;
    const int lane = t & 31;
    const int bm = blockIdx.y * 128;
    const int bn = blockIdx.x * 128;
    const int z  = blockIdx.z;
    const __nv_bfloat16* bhi = Bhi_all + (size_t)z * DIM * DIM;
    const __nv_bfloat16* blo = Blo_all + (size_t)z * DIM * DIM;
    float* C = (z == 0) ? C0 : (z == 1 ? C1 : C2);

    const int wm = (wid >> 2) * 64;
    const int wn = (wid & 3) * 32;

    float acc[4][4][4];
#pragma unroll
    for (int i = 0; i < 4; i++)
#pragma unroll
        for (int j = 0; j < 4; j++)
#pragma unroll
            for (int r = 0; r < 4; r++) acc[i][j][r] = 0.0f;

    auto issue_chunk = [&](int kc, int stage) {
        const uint32_t sbase = sb + stage * STAGEB;
#pragma unroll
        for (int i = 0; i < 8; i++) {
            int id   = t + 256 * i;
            int tile = id >> 9;
            int w    = id & 511;
            int row  = w >> 2;
            int cg   = (w & 3) * 8;
            uint32_t so = sbase + tile * TILEB + (uint32_t)(row * SKB + cg) * 2;
            const __nv_bfloat16* gp;
            if (tile == 0)      gp = Ahi + (size_t)(bm + row) * DIM + kc + cg;
            else if (tile == 1) gp = Alo + (size_t)(bm + row) * DIM + kc + cg;
            else if (tile == 2) gp = bhi + (size_t)(bn + row) * DIM + kc + cg;
            else                gp = blo + (size_t)(bn + row) * DIM + kc + cg;
            CP_ASYNC16(so, gp);
        }
        CP_COMMIT();
    };

    issue_chunk(0, 0);

    const int lrow = lane & 7;
    const int seg  = lane >> 3;

    for (int c = 0; c < NCHUNK; c++) {
        CP_WAIT(0);
        __syncthreads();
        if (c + 1 < NCHUNK) issue_chunk((c + 1) * 32, (c + 1) & 1);

        const uint32_t stg = sb + (c & 1) * STAGEB;
#pragma unroll
        for (int ks = 0; ks < 32; ks += 16) {
            uint32_t bh[2][4], bl[2][4];
#pragma unroll
            for (int p = 0; p < 2; p++) {
                int br = wn + p * 16 + (seg >> 1) * 8 + lrow;
                int bc = ks + (seg & 1) * 8;
                uint32_t off = (uint32_t)(br * SKB + bc) * 2;
                ldsm_x4(bh[p], stg + 2 * TILEB + off);
                ldsm_x4(bl[p], stg + 3 * TILEB + off);
            }
#pragma unroll
            for (int mt = 0; mt < 4; mt++) {
                int ar = wm + mt * 16 + (seg & 1) * 8 + lrow;
                int ac = ks + (seg >> 1) * 8;
                uint32_t off = (uint32_t)(ar * SKB + ac) * 2;
                uint32_t ah[4], al[4];
                ldsm_x4(ah, stg + 0 * TILEB + off);
                ldsm_x4(al, stg + 1 * TILEB + off);
#pragma unroll
                for (int nt = 0; nt < 4; nt++) {
                    int p = nt >> 1, q = (nt & 1) * 2;
                    mma_bf16(acc[mt][nt], ah, bh[p][q], bh[p][q + 1]);
                    mma_bf16(acc[mt][nt], ah, bl[p][q], bl[p][q + 1]);
                    mma_bf16(acc[mt][nt], al, bh[p][q], bh[p][q + 1]);
                }
            }
        }
        __syncthreads();
    }

    const int trow = lane >> 2;
    const int tcol = (lane & 3) * 2;
#pragma unroll
    for (int mt = 0; mt < 4; mt++) {
#pragma unroll
        for (int nt = 0; nt < 4; nt++) {
            size_t r0 = (size_t)(bm + wm + mt * 16 + trow);
            size_t cc = (size_t)(bn + wn + nt * 8 + tcol);
            *(float2*)(C + r0 * DIM + cc) =
                make_float2(acc[mt][nt][0], acc[mt][nt][1]);
            *(float2*)(C + (r0 + 8) * DIM + cc) =
                make_float2(acc[mt][nt][2], acc[mt][nt][3]);
        }
    }
}

// ---------------- RoPE (unchanged, validated) ------------------------------
__global__ void rope_kernel(float* __restrict__ q, float* __restrict__ k)
{
    int idx = blockIdx.x * blockDim.x + threadIdx.x;
    if (idx >= S_LEN * NH * (HD / 2)) return;
    int j = idx & 31;
    int h = (idx >> 5) & 15;
    int s = idx >> 9;

    float inv_freq = 1.0f / powf(10000.0f, (float)(2 * j) * (1.0f / 64.0f));
    float ang = (float)s * inv_freq;
    float c = cosf(ang), sn = sinf(ang);

    int base = s * DIM + h * HD + 2 * j;
    {
        float x1 = q[base], x2 = q[base + 1];
        q[base]     = x1 * c - x2 * sn;
        q[base + 1] = x1 * sn + x2 * c;
    }
    {
        float x1 = k[base], x2 = k[base + 1];
        k[base]     = x1 * c - x2 * sn;
        k[base + 1] = x1 * sn + x2 * c;
    }
}

// ---------------- HMMA split-bf16 sliding-window flash attention -----------
// CTA = (q-tile 128, head), 256 thr / 8 warps. Warp owns 16 q-rows x full
// 128-key tile (no cross-warp softmax). S and PV both use 3-term hi/lo split.
#define SKD 72
#define ATN_Q_HI 0
#define ATN_Q_LO 18432
#define ATN_K_HI 36864
#define ATN_K_LO 55296
#define ATN_V_HI 73728
#define ATN_V_LO 92160
#define ATN_SMEM 110592

__global__ __launch_bounds__(256, 1) void attn_hmma(
    const __nv_bfloat16* __restrict__ qhi, const __nv_bfloat16* __restrict__ qlo,
    const __nv_bfloat16* __restrict__ khi, const __nv_bfloat16* __restrict__ klo,
    const __nv_bfloat16* __restrict__ vhi, const __nv_bfloat16* __restrict__ vlo,
    float* __restrict__ o)
{
    extern __shared__ char sms[];
    const uint32_t sb = smem_u32(sms);
    const int t = threadIdx.x;
    const int lane = t & 31;
    const int wid  = t >> 5;
    const int h  = blockIdx.y;
    const int qs = blockIdx.x * 128;
    const int lrow = lane & 7;
    const int seg  = lane >> 3;

    // Fill Q smem (hi/lo): 128 rows x 64 halves, row stride SKD halves
#pragma unroll
    for (int i = 0; i < 4; i++) {
        int f = i * 256 + t;
        int r = f >> 3, cg = (f & 7) * 8;
        uint32_t so = (uint32_t)(r * SKD + cg) * 2;
        size_t g = (size_t)(qs + r) * DIM + h * HD + cg;
        *(uint4*)(sms + ATN_Q_HI + so) = *(const uint4*)(qhi + g);
        *(uint4*)(sms + ATN_Q_LO + so) = *(const uint4*)(qlo + g);
    }
    __syncthreads();

    // Hoist Q A-fragments (4 k16-steps, hi/lo)
    uint32_t aQh[4][4], aQl[4][4];
    {
        int ar = wid * 16 + (seg & 1) * 8 + lrow;
#pragma unroll
        for (int ks = 0; ks < 4; ks++) {
            int ac = ks * 16 + (seg >> 1) * 8;
            uint32_t off = (uint32_t)(ar * SKD + ac) * 2;
            ldsm_x4(aQh[ks], sb + ATN_Q_HI + off);
            ldsm_x4(aQl[ks], sb + ATN_Q_LO + off);
        }
    }

    float m0 = -1e30f, m1 = -1e30f, l0 = 0.0f, l1 = 0.0f;
    float oa[8][4];
#pragma unroll
    for (int i = 0; i < 8; i++)
#pragma unroll
        for (int j = 0; j < 4; j++) oa[i][j] = 0.0f;

    const int r0 = wid * 16 + (lane >> 2);    // local q row (and r0+8)
    const int qg0 = qs + r0;
    const int qg1 = qg0 + 8;

    int kt0 = qs - WIN;
    if (kt0 < 0) kt0 = 0;

    for (int kt = kt0; kt <= qs; kt += 128) {
        __syncthreads();   // previous iteration's ldsm reads done
        // Fill K/V smem (hi/lo)
#pragma unroll
        for (int i = 0; i < 4; i++) {
            int f = i * 256 + t;
            int r = f >> 3, cg = (f & 7) * 8;
            uint32_t so = (uint32_t)(r * SKD + cg) * 2;
            size_t g = (size_t)(kt + r) * DIM + h * HD + cg;
            *(uint4*)(sms + ATN_K_HI + so) = *(const uint4*)(khi + g);
            *(uint4*)(sms + ATN_K_LO + so) = *(const uint4*)(klo + g);
            *(uint4*)(sms + ATN_V_HI + so) = *(const uint4*)(vhi + g);
            *(uint4*)(sms + ATN_V_LO + so) = *(const uint4*)(vlo + g);
        }
        __syncthreads();

        // ---- S = Q K^T (split, fp32 accum) ----
        float sc[16][4];
#pragma unroll
        for (int i = 0; i < 16; i++)
#pragma unroll
            for (int j = 0; j < 4; j++) sc[i][j] = 0.0f;

#pragma unroll
        for (int ks = 0; ks < 4; ks++) {
#pragma unroll
            for (int bp = 0; bp < 8; bp++) {
                uint32_t bh[4], bl[4];
                int br = bp * 16 + (seg >> 1) * 8 + lrow;
                int bc = ks * 16 + (seg & 1) * 8;
                uint32_t off = (uint32_t)(br * SKD + bc) * 2;
                ldsm_x4(bh, sb + ATN_K_HI + off);
                ldsm_x4(bl, sb + ATN_K_LO + off);
                mma_bf16(sc[2 * bp],     aQh[ks], bh[0], bh[1]);
                mma_bf16(sc[2 * bp],     aQh[ks], bl[0], bl[1]);
                mma_bf16(sc[2 * bp],     aQl[ks], bh[0], bh[1]);
                mma_bf16(sc[2 * bp + 1], aQh[ks], bh[2], bh[3]);
                mma_bf16(sc[2 * bp + 1], aQh[ks], bl[2], bl[3]);
                mma_bf16(sc[2 * bp + 1], aQl[ks], bh[2], bh[3]);
            }
        }

        // ---- scale + mask + online softmax ----
        float nm0 = m0, nm1 = m1;
#pragma unroll
        for (int nt = 0; nt < 16; nt++) {
            int kg = kt + nt * 8 + (lane & 3) * 2;
            sc[nt][0] = (kg     <= qg0 && kg     > qg0 - WIN) ? sc[nt][0] * 0.125f : -1e30f;
            sc[nt][1] = (kg + 1 <= qg0 && kg + 1 > qg0 - WIN) ? sc[nt][1] * 0.125f : -1e30f;
            sc[nt][2] = (kg     <= qg1 && kg     > qg1 - WIN) ? sc[nt][2] * 0.125f : -1e30f;
            sc[nt][3] = (kg + 1 <= qg1 && kg + 1 > qg1 - WIN) ? sc[nt][3] * 0.125f : -1e30f;
            nm0 = fmaxf(nm0, fmaxf(sc[nt][0], sc[nt][1]));
            nm1 = fmaxf(nm1, fmaxf(sc[nt][2], sc[nt][3]));
        }
        nm0 = fmaxf(nm0, __shfl_xor_sync(0xffffffffu, nm0, 1));
        nm0 = fmaxf(nm0, __shfl_xor_sync(0xffffffffu, nm0, 2));
        nm1 = fmaxf(nm1, __shfl_xor_sync(0xffffffffu, nm1, 1));
        nm1 = fmaxf(nm1, __shfl_xor_sync(0xffffffffu, nm1, 2));

        float al0 = __expf(m0 - nm0);
        float al1 = __expf(m1 - nm1);
        m0 = nm0; m1 = nm1;

        float rs0 = 0.0f, rs1 = 0.0f;
#pragma unroll
        for (int nt = 0; nt < 16; nt++) {
            float p0 = (sc[nt][0] > -1e29f) ? __expf(sc[nt][0] - m0) : 0.0f;
            float p1 = (sc[nt][1] > -1e29f) ? __expf(sc[nt][1] - m0) : 0.0f;
            float p2 = (sc[nt][2] > -1e29f) ? __expf(sc[nt][2] - m1) : 0.0f;
            float p3 = (sc[nt][3] > -1e29f) ? __expf(sc[nt][3] - m1) : 0.0f;
            sc[nt][0] = p0; sc[nt][1] = p1; sc[nt][2] = p2; sc[nt][3] = p3;
            rs0 += p0 + p1;
            rs1 += p2 + p3;
        }
        rs0 += __shfl_xor_sync(0xffffffffu, rs0, 1);
        rs0 += __shfl_xor_sync(0xffffffffu, rs0, 2);
        rs1 += __shfl_xor_sync(0xffffffffu, rs1, 1);
        rs1 += __shfl_xor_sync(0xffffffffu, rs1, 2);
        l0 = l0 * al0 + rs0;
        l1 = l1 * al1 + rs1;

#pragma unroll
        for (int i = 0; i < 8; i++) {
            oa[i][0] *= al0; oa[i][1] *= al0;
            oa[i][2] *= al1; oa[i][3] *= al1;
        }

        // ---- O += P V (split P hi/lo, V hi/lo; 3 terms) ----
#pragma unroll
        for (int j = 0; j < 8; j++) {
            // A-frags from P (C-fragment repack): tiles 2j, 2j+1 cover k16
            float p00 = sc[2 * j][0],     p01 = sc[2 * j][1];
            float p02 = sc[2 * j][2],     p03 = sc[2 * j][3];
            float p10 = sc[2 * j + 1][0], p11 = sc[2 * j + 1][1];
            float p12 = sc[2 * j + 1][2], p13 = sc[2 * j + 1][3];
            uint32_t pah[4], pal[4];
            {
                __nv_bfloat16 h00 = __float2bfloat16(p00), h01 = __float2bfloat16(p01);
                __nv_bfloat16 h02 = __float2bfloat16(p02), h03 = __float2bfloat16(p03);
                __nv_bfloat16 h10 = __float2bfloat16(p10), h11 = __float2bfloat16(p11);
                __nv_bfloat16 h12 = __float2bfloat16(p12), h13 = __float2bfloat16(p13);
                pah[0] = (uint32_t)__bfloat16_as_ushort(h00) | ((uint32_t)__bfloat16_as_ushort(h01) << 16);
                pah[1] = (uint32_t)__bfloat16_as_ushort(h02) | ((uint32_t)__bfloat16_as_ushort(h03) << 16);
                pah[2] = (uint32_t)__bfloat16_as_ushort(h10) | ((uint32_t)__bfloat16_as_ushort(h11) << 16);
                pah[3] = (uint32_t)__bfloat16_as_ushort(h12) | ((uint32_t)__bfloat16_as_ushort(h13) << 16);
                pal[0] = pack_bf2(p00 - __bfloat162float(h00), p01 - __bfloat162float(h01));
                pal[1] = pack_bf2(p02 - __bfloat162float(h02), p03 - __bfloat162float(h03));
                pal[2] = pack_bf2(p10 - __bfloat162float(h10), p11 - __bfloat162float(h11));
                pal[3] = pack_bf2(p12 - __bfloat162float(h12), p13 - __bfloat162float(h13));
            }
#pragma unroll
            for (int dp = 0; dp < 4; dp++) {
                uint32_t bh[4], bl[4];
                int kk = j * 16 + (seg & 1) * 8 + lrow;
                int nn = dp * 16 + (seg >> 1) * 8;
                uint32_t off = (uint32_t)(kk * SKD + nn) * 2;
                ldsm_x4_trans(bh, sb + ATN_V_HI + off);
                ldsm_x4_trans(bl, sb + ATN_V_LO + off);
                mma_bf16(oa[dp * 2],     pah, bh[0], bh[1]);
                mma_bf16(oa[dp * 2],     pah, bl[0], bl[1]);
                mma_bf16(oa[dp * 2],     pal, bh[0], bh[1]);
                mma_bf16(oa[dp * 2 + 1], pah, bh[2], bh[3]);
                mma_bf16(oa[dp * 2 + 1], pah, bl[2], bl[3]);
                mma_bf16(oa[dp * 2 + 1], pal, bh[2], bh[3]);
            }
        }
    }

    // Epilogue: normalize, write fp32 O
    float inv0 = 1.0f / l0;
    float inv1 = 1.0f / l1;
    const int tcol = (lane & 3) * 2;
#pragma unroll
    for (int dt = 0; dt < 8; dt++) {
        size_t c = (size_t)(h * HD + dt * 8 + tcol);
        *(float2*)(o + (size_t)qg0 * DIM + c) =
            make_float2(oa[dt][0] * inv0, oa[dt][1] * inv0);
        *(float2*)(o + (size_t)qg1 * DIM + c) =
            make_float2(oa[dt][2] * inv1, oa[dt][3] * inv1);
    }
}

// ---------------------------------------------------------------------------
extern "C" void kernel_launch(void* const* d_in, const int* in_sizes, int n_in,
                              void* d_out, int out_size)
{
    const float* x  = (const float*)d_in[0];
    const float* Wq = (const float*)d_in[1];
    const float* Wk = (const float*)d_in[2];
    const float* Wv = (const float*)d_in[3];
    const float* Wo = (const float*)d_in[4];
    float* out = (float*)d_out;

    float *q, *k, *v, *o;
    __nv_bfloat16 *xhi, *xlo, *whi, *wlo, *ohi, *olo;
    __nv_bfloat16 *qhi, *qlo, *khi, *klo, *vhi, *vlo;
    cudaGetSymbolAddress((void**)&q, g_q);
    cudaGetSymbolAddress((void**)&k, g_k);
    cudaGetSymbolAddress((void**)&v, g_v);
    cudaGetSymbolAddress((void**)&o, g_o);
    cudaGetSymbolAddress((void**)&xhi, g_xhi);
    cudaGetSymbolAddress((void**)&xlo, g_xlo);
    cudaGetSymbolAddress((void**)&whi, g_whi);
    cudaGetSymbolAddress((void**)&wlo, g_wlo);
    cudaGetSymbolAddress((void**)&ohi, g_ohi);
    cudaGetSymbolAddress((void**)&olo, g_olo);
    cudaGetSymbolAddress((void**)&qhi, g_qhi);
    cudaGetSymbolAddress((void**)&qlo, g_qlo);
    cudaGetSymbolAddress((void**)&khi, g_khi);
    cudaGetSymbolAddress((void**)&klo, g_klo);
    cudaGetSymbolAddress((void**)&vhi, g_vhi);
    cudaGetSymbolAddress((void**)&vlo, g_vlo);

    cudaFuncSetAttribute(gemm_hmma,
                         cudaFuncAttributeMaxDynamicSharedMemorySize, GEMM_SMEM);
    cudaFuncSetAttribute(attn_hmma,
                         cudaFuncAttributeMaxDynamicSharedMemorySize, ATN_SMEM);

    // 1) Split x and weights into bf16 hi/lo
    {
        int n4 = S_LEN * DIM / 4;
        split2_kernel<<<(n4 + 255) / 256, 256>>>(x, xhi, xlo, n4);
        int w4 = DIM * DIM / 4;
        split2_kernel<<<(w4 + 255) / 256, 256>>>(Wq, whi + 0 * DIM * DIM, wlo + 0 * DIM * DIM, w4);
        split2_kernel<<<(w4 + 255) / 256, 256>>>(Wk, whi + 1 * DIM * DIM, wlo + 1 * DIM * DIM, w4);
        split2_kernel<<<(w4 + 255) / 256, 256>>>(Wv, whi + 2 * DIM * DIM, wlo + 2 * DIM * DIM, w4);
        split2_kernel<<<(w4 + 255) / 256, 256>>>(Wo, whi + 3 * DIM * DIM, wlo + 3 * DIM * DIM, w4);
    }

    // 2) Fused Q/K/V projections (HMMA split-fp32)
    gemm_hmma<<<dim3(DIM / 128, S_LEN / 128, 3), 256, GEMM_SMEM>>>(
        xhi, xlo, whi, wlo, q, k, v);

    // 3) RoPE on q and k (in place, fp32)
    int rope_n = S_LEN * NH * (HD / 2);
    rope_kernel<<<(rope_n + 255) / 256, 256>>>(q, k);

    // 4) Split q/k/v into bf16 hi/lo for attention
    {
        int n4 = S_LEN * DIM / 4;
        split2_kernel<<<(n4 + 255) / 256, 256>>>(q, qhi, qlo, n4);
        split2_kernel<<<(n4 + 255) / 256, 256>>>(k, khi, klo, n4);
        split2_kernel<<<(n4 + 255) / 256, 256>>>(v, vhi, vlo, n4);
    }

    // 5) Sliding-window attention (HMMA split-bf16)
    attn_hmma<<<dim3(S_LEN / 128, NH), 256, ATN_SMEM>>>(
        qhi, qlo, khi, klo, vhi, vlo, o);

    // 6) Split attention output, then output projection (HMMA split-fp32)
    {
        int n4 = S_LEN * DIM / 4;
        split2_kernel<<<(n4 + 255) / 256, 256>>>(o, ohi, olo, n4);
    }
    gemm_hmma<<<dim3(DIM / 128, S_LEN / 128, 1), 256, GEMM_SMEM>>>(
        ohi, olo, whi + 3 * DIM * DIM, wlo + 3 * DIM * DIM, out, out, out);
}

// round 10
// speedup vs baseline: 2.3532x; 1.0441x over previous
#include <cuda_runtime.h>
#include <cuda_bf16.h>
#include <math.h>
#include <cstdint>

#define S_LEN 8192
#define DIM   1024
#define NH    16
#define HD    64
#define WIN   512

// ---------------- scratch (allocation-free rule: device globals) ----------
__device__ __align__(256) __nv_bfloat16 g_xhi[S_LEN * DIM];
__device__ __align__(256) __nv_bfloat16 g_xlo[S_LEN * DIM];
__device__ __align__(256) __nv_bfloat16 g_whi[4 * DIM * DIM];
__device__ __align__(256) __nv_bfloat16 g_wlo[4 * DIM * DIM];
__device__ __align__(256) __nv_bfloat16 g_qhi[S_LEN * DIM];
__device__ __align__(256) __nv_bfloat16 g_qlo[S_LEN * DIM];
__device__ __align__(256) __nv_bfloat16 g_khi[S_LEN * DIM];
__device__ __align__(256) __nv_bfloat16 g_klo[S_LEN * DIM];
__device__ __align__(256) __nv_bfloat16 g_vhi[S_LEN * DIM];
__device__ __align__(256) __nv_bfloat16 g_vlo[S_LEN * DIM];
__device__ __align__(256) __nv_bfloat16 g_ohi[S_LEN * DIM];
__device__ __align__(256) __nv_bfloat16 g_olo[S_LEN * DIM];

// ---------------- fp32 -> bf16 hi/lo split --------------------------------
__global__ void split2_kernel(const float* __restrict__ src,
                              __nv_bfloat16* __restrict__ hi,
                              __nv_bfloat16* __restrict__ lo, int n4)
{
    int i = blockIdx.x * blockDim.x + threadIdx.x;
    if (i >= n4) return;
    float4 x = ((const float4*)src)[i];
    __nv_bfloat16 h0 = __float2bfloat16(x.x);
    __nv_bfloat16 h1 = __float2bfloat16(x.y);
    __nv_bfloat16 h2 = __float2bfloat16(x.z);
    __nv_bfloat16 h3 = __float2bfloat16(x.w);
    __nv_bfloat16 l0 = __float2bfloat16(x.x - __bfloat162float(h0));
    __nv_bfloat16 l1 = __float2bfloat16(x.y - __bfloat162float(h1));
    __nv_bfloat16 l2 = __float2bfloat16(x.z - __bfloat162float(h2));
    __nv_bfloat16 l3 = __float2bfloat16(x.w - __bfloat162float(h3));
    uint2 uh, ul;
    uh.x = (uint32_t)__bfloat16_as_ushort(h0) | ((uint32_t)__bfloat16_as_ushort(h1) << 16);
    uh.y = (uint32_t)__bfloat16_as_ushort(h2) | ((uint32_t)__bfloat16_as_ushort(h3) << 16);
    ul.x = (uint32_t)__bfloat16_as_ushort(l0) | ((uint32_t)__bfloat16_as_ushort(l1) << 16);
    ul.y = (uint32_t)__bfloat16_as_ushort(l2) | ((uint32_t)__bfloat16_as_ushort(l3) << 16);
    ((uint2*)hi)[i] = uh;
    ((uint2*)lo)[i] = ul;
}

// ---------------- HMMA helpers --------------------------------------------
__device__ __forceinline__ uint32_t smem_u32(const void* p) {
    uint32_t a;
    asm("{ .reg .u64 t; cvta.to.shared.u64 t, %1; cvt.u32.u64 %0, t; }"
        : "=r"(a) : "l"(p));
    return a;
}
__device__ __forceinline__ void ldsm_x4(uint32_t* r, uint32_t saddr) {
    asm volatile("ldmatrix.sync.aligned.m8n8.x4.shared.b16 {%0,%1,%2,%3}, [%4];"
                 : "=r"(r[0]), "=r"(r[1]), "=r"(r[2]), "=r"(r[3]) : "r"(saddr));
}
__device__ __forceinline__ void ldsm_x4_trans(uint32_t* r, uint32_t saddr) {
    asm volatile("ldmatrix.sync.aligned.m8n8.x4.trans.shared.b16 {%0,%1,%2,%3}, [%4];"
                 : "=r"(r[0]), "=r"(r[1]), "=r"(r[2]), "=r"(r[3]) : "r"(saddr));
}
__device__ __forceinline__ void mma_bf16(float* c, const uint32_t* a,
                                         uint32_t b0, uint32_t b1) {
    asm volatile(
        "mma.sync.aligned.m16n8k16.row.col.f32.bf16.bf16.f32 "
        "{%0,%1,%2,%3}, {%4,%5,%6,%7}, {%8,%9}, {%0,%1,%2,%3};"
        : "+f"(c[0]), "+f"(c[1]), "+f"(c[2]), "+f"(c[3])
        : "r"(a[0]), "r"(a[1]), "r"(a[2]), "r"(a[3]), "r"(b0), "r"(b1));
}
#define CP_ASYNC16(saddr, gptr) \
    asm volatile("cp.async.ca.shared.global [%0], [%1], 16;" \
                 :: "r"(saddr), "l"(gptr))
#define CP_COMMIT()  asm volatile("cp.async.commit_group;" ::: "memory")
#define CP_WAIT(n)   asm volatile("cp.async.wait_group %0;" :: "n"(n) : "memory")

// pack two floats -> bf16x2 word
__device__ __forceinline__ uint32_t pack_bf2(float x, float y) {
    __nv_bfloat16 bx = __float2bfloat16(x), by = __float2bfloat16(y);
    return (uint32_t)__bfloat16_as_ushort(bx) |
           ((uint32_t)__bfloat16_as_ushort(by) << 16);
}
// split pair of floats into hi word + lo word
__device__ __forceinline__ void split_pair(float x, float y,
                                           uint32_t& hw, uint32_t& lw) {
    __nv_bfloat16 hx = __float2bfloat16(x), hy = __float2bfloat16(y);
    hw = (uint32_t)__bfloat16_as_ushort(hx) |
         ((uint32_t)__bfloat16_as_ushort(hy) << 16);
    lw = pack_bf2(x - __bfloat162float(hx), y - __bfloat162float(hy));
}

// ---------------- HMMA split-fp32 GEMM NT ----------------------------------
// FS=true: epilogue applies RoPE (z<2) and writes bf16 hi/lo (fused split).
// FS=false: epilogue writes fp32 C0.
#define SKB   40
#define TILEB (128 * SKB * 2)
#define STAGEB (4 * TILEB)
#define GEMM_SMEM (2 * STAGEB)
#define NCHUNK (DIM / 32)

template <bool FS>
__global__ __launch_bounds__(256)
void gemm_hmma(const __nv_bfloat16* __restrict__ Ahi,
               const __nv_bfloat16* __restrict__ Alo,
               const __nv_bfloat16* __restrict__ Bhi_all,
               const __nv_bfloat16* __restrict__ Blo_all,
               float* __restrict__ C0,
               __nv_bfloat16* __restrict__ H0, __nv_bfloat16* __restrict__ L0,
               __nv_bfloat16* __restrict__ H1, __nv_bfloat16* __restrict__ L1,
               __nv_bfloat16* __restrict__ H2, __nv_bfloat16* __restrict__ L2)
{
    extern __shared__ char smem[];
    const uint32_t sb = smem_u32(smem);
    const int t    = threadIdx.x;
    const int wid  = t >> 5;
    const int lane = t & 31;
    const int bm = blockIdx.y * 128;
    const int bn = blockIdx.x * 128;
    const int z  = blockIdx.z;
    const __nv_bfloat16* bhi = Bhi_all + (size_t)z * DIM * DIM;
    const __nv_bfloat16* blo = Blo_all + (size_t)z * DIM * DIM;

    const int wm = (wid >> 2) * 64;
    const int wn = (wid & 3) * 32;

    float acc[4][4][4];
#pragma unroll
    for (int i = 0; i < 4; i++)
#pragma unroll
        for (int j = 0; j < 4; j++)
#pragma unroll
            for (int r = 0; r < 4; r++) acc[i][j][r] = 0.0f;

    auto issue_chunk = [&](int kc, int stage) {
        const uint32_t sbase = sb + stage * STAGEB;
#pragma unroll
        for (int i = 0; i < 8; i++) {
            int id   = t + 256 * i;
            int tile = id >> 9;
            int w    = id & 511;
            int row  = w >> 2;
            int cg   = (w & 3) * 8;
            uint32_t so = sbase + tile * TILEB + (uint32_t)(row * SKB + cg) * 2;
            const __nv_bfloat16* gp;
            if (tile == 0)      gp = Ahi + (size_t)(bm + row) * DIM + kc + cg;
            else if (tile == 1) gp = Alo + (size_t)(bm + row) * DIM + kc + cg;
            else if (tile == 2) gp = bhi + (size_t)(bn + row) * DIM + kc + cg;
            else                gp = blo + (size_t)(bn + row) * DIM + kc + cg;
            CP_ASYNC16(so, gp);
        }
        CP_COMMIT();
    };

    issue_chunk(0, 0);

    const int lrow = lane & 7;
    const int seg  = lane >> 3;

    for (int c = 0; c < NCHUNK; c++) {
        CP_WAIT(0);
        __syncthreads();
        if (c + 1 < NCHUNK) issue_chunk((c + 1) * 32, (c + 1) & 1);

        const uint32_t stg = sb + (c & 1) * STAGEB;
#pragma unroll
        for (int ks = 0; ks < 32; ks += 16) {
            uint32_t bh[2][4], bl[2][4];
#pragma unroll
            for (int p = 0; p < 2; p++) {
                int br = wn + p * 16 + (seg >> 1) * 8 + lrow;
                int bc = ks + (seg & 1) * 8;
                uint32_t off = (uint32_t)(br * SKB + bc) * 2;
                ldsm_x4(bh[p], stg + 2 * TILEB + off);
                ldsm_x4(bl[p], stg + 3 * TILEB + off);
            }
#pragma unroll
            for (int mt = 0; mt < 4; mt++) {
                int ar = wm + mt * 16 + (seg & 1) * 8 + lrow;
                int ac = ks + (seg >> 1) * 8;
                uint32_t off = (uint32_t)(ar * SKB + ac) * 2;
                uint32_t ah[4], al[4];
                ldsm_x4(ah, stg + 0 * TILEB + off);
                ldsm_x4(al, stg + 1 * TILEB + off);
#pragma unroll
                for (int nt = 0; nt < 4; nt++) {
                    int p = nt >> 1, q = (nt & 1) * 2;
                    mma_bf16(acc[mt][nt], ah, bh[p][q], bh[p][q + 1]);
                    mma_bf16(acc[mt][nt], ah, bl[p][q], bl[p][q + 1]);
                    mma_bf16(acc[mt][nt], al, bh[p][q], bh[p][q + 1]);
                }
            }
        }
        __syncthreads();
    }

    const int trow = lane >> 2;
    const int tcol = (lane & 3) * 2;

    if (!FS) {
        // fp32 epilogue (final output projection)
#pragma unroll
        for (int mt = 0; mt < 4; mt++) {
#pragma unroll
            for (int nt = 0; nt < 4; nt++) {
                size_t r0 = (size_t)(bm + wm + mt * 16 + trow);
                size_t cc = (size_t)(bn + wn + nt * 8 + tcol);
                *(float2*)(C0 + r0 * DIM + cc) =
                    make_float2(acc[mt][nt][0], acc[mt][nt][1]);
                *(float2*)(C0 + (r0 + 8) * DIM + cc) =
                    make_float2(acc[mt][nt][2], acc[mt][nt][3]);
            }
        }
    } else {
        // Fused RoPE (q,k only) + hi/lo split epilogue
        __nv_bfloat16* Hp = (z == 0) ? H0 : (z == 1 ? H1 : H2);
        __nv_bfloat16* Lp = (z == 0) ? L0 : (z == 1 ? L1 : L2);
        const bool rope = (z != 2);
#pragma unroll
        for (int nt = 0; nt < 4; nt++) {
            int cc = bn + wn + nt * 8 + tcol;
            float invf = 0.0f;
            if (rope) {
                int j = (cc & 63) >> 1;
                invf = 1.0f / powf(10000.0f, (float)(2 * j) * (1.0f / 64.0f));
            }
#pragma unroll
            for (int mt = 0; mt < 4; mt++) {
                int r0 = bm + wm + mt * 16 + trow;
                float a0 = acc[mt][nt][0], a1 = acc[mt][nt][1];
                float a2 = acc[mt][nt][2], a3 = acc[mt][nt][3];
                if (rope) {
                    float s0, c0, s1, c1;
                    sincosf((float)r0 * invf, &s0, &c0);
                    sincosf((float)(r0 + 8) * invf, &s1, &c1);
                    float n0 = a0 * c0 - a1 * s0;
                    float n1 = a0 * s0 + a1 * c0;
                    float n2 = a2 * c1 - a3 * s1;
                    float n3 = a2 * s1 + a3 * c1;
                    a0 = n0; a1 = n1; a2 = n2; a3 = n3;
                }
                uint32_t hw0, lw0, hw1, lw1;
                split_pair(a0, a1, hw0, lw0);
                split_pair(a2, a3, hw1, lw1);
                size_t base0 = (size_t)r0 * DIM + cc;
                size_t base1 = (size_t)(r0 + 8) * DIM + cc;
                *(uint32_t*)(Hp + base0) = hw0;
                *(uint32_t*)(Lp + base0) = lw0;
                *(uint32_t*)(Hp + base1) = hw1;
                *(uint32_t*)(Lp + base1) = lw1;
            }
        }
    }
}

// ---------------- HMMA split-bf16 sliding-window flash attention -----------
// CTA = (q-tile 128, head), 256 thr / 8 warps. Warp owns 16 q-rows x full
// 128-key tile. S and PV both 3-term hi/lo split. Epilogue writes bf16 hi/lo.
#define SKD 72
#define ATN_Q_HI 0
#define ATN_Q_LO 18432
#define ATN_K_HI 36864
#define ATN_K_LO 55296
#define ATN_V_HI 73728
#define ATN_V_LO 92160
#define ATN_SMEM 110592

__global__ __launch_bounds__(256, 1) void attn_hmma(
    const __nv_bfloat16* __restrict__ qhi, const __nv_bfloat16* __restrict__ qlo,
    const __nv_bfloat16* __restrict__ khi, const __nv_bfloat16* __restrict__ klo,
    const __nv_bfloat16* __restrict__ vhi, const __nv_bfloat16* __restrict__ vlo,
    __nv_bfloat16* __restrict__ ohi, __nv_bfloat16* __restrict__ olo)
{
    extern __shared__ char sms[];
    const uint32_t sb = smem_u32(sms);
    const int t = threadIdx.x;
    const int lane = t & 31;
    const int wid  = t >> 5;
    const int h  = blockIdx.y;
    const int qs = blockIdx.x * 128;
    const int lrow = lane & 7;
    const int seg  = lane >> 3;

#pragma unroll
    for (int i = 0; i < 4; i++) {
        int f = i * 256 + t;
        int r = f >> 3, cg = (f & 7) * 8;
        uint32_t so = (uint32_t)(r * SKD + cg) * 2;
        size_t g = (size_t)(qs + r) * DIM + h * HD + cg;
        *(uint4*)(sms + ATN_Q_HI + so) = *(const uint4*)(qhi + g);
        *(uint4*)(sms + ATN_Q_LO + so) = *(const uint4*)(qlo + g);
    }
    __syncthreads();

    uint32_t aQh[4][4], aQl[4][4];
    {
        int ar = wid * 16 + (seg & 1) * 8 + lrow;
#pragma unroll
        for (int ks = 0; ks < 4; ks++) {
            int ac = ks * 16 + (seg >> 1) * 8;
            uint32_t off = (uint32_t)(ar * SKD + ac) * 2;
            ldsm_x4(aQh[ks], sb + ATN_Q_HI + off);
            ldsm_x4(aQl[ks], sb + ATN_Q_LO + off);
        }
    }

    float m0 = -1e30f, m1 = -1e30f, l0 = 0.0f, l1 = 0.0f;
    float oa[8][4];
#pragma unroll
    for (int i = 0; i < 8; i++)
#pragma unroll
        for (int j = 0; j < 4; j++) oa[i][j] = 0.0f;

    const int r0 = wid * 16 + (lane >> 2);
    const int qg0 = qs + r0;
    const int qg1 = qg0 + 8;

    int kt0 = qs - WIN;
    if (kt0 < 0) kt0 = 0;

    for (int kt = kt0; kt <= qs; kt += 128) {
        __syncthreads();
#pragma unroll
        for (int i = 0; i < 4; i++) {
            int f = i * 256 + t;
            int r = f >> 3, cg = (f & 7) * 8;
            uint32_t so = (uint32_t)(r * SKD + cg) * 2;
            size_t g = (size_t)(kt + r) * DIM + h * HD + cg;
            *(uint4*)(sms + ATN_K_HI + so) = *(const uint4*)(khi + g);
            *(uint4*)(sms + ATN_K_LO + so) = *(const uint4*)(klo + g);
            *(uint4*)(sms + ATN_V_HI + so) = *(const uint4*)(vhi + g);
            *(uint4*)(sms + ATN_V_LO + so) = *(const uint4*)(vlo + g);
        }
        __syncthreads();

        float sc[16][4];
#pragma unroll
        for (int i = 0; i < 16; i++)
#pragma unroll
            for (int j = 0; j < 4; j++) sc[i][j] = 0.0f;

#pragma unroll
        for (int ks = 0; ks < 4; ks++) {
#pragma unroll
            for (int bp = 0; bp < 8; bp++) {
                uint32_t bh[4], bl[4];
                int br = bp * 16 + (seg >> 1) * 8 + lrow;
                int bc = ks * 16 + (seg & 1) * 8;
                uint32_t off = (uint32_t)(br * SKD + bc) * 2;
                ldsm_x4(bh, sb + ATN_K_HI + off);
                ldsm_x4(bl, sb + ATN_K_LO + off);
                mma_bf16(sc[2 * bp],     aQh[ks], bh[0], bh[1]);
                mma_bf16(sc[2 * bp],     aQh[ks], bl[0], bl[1]);
                mma_bf16(sc[2 * bp],     aQl[ks], bh[0], bh[1]);
                mma_bf16(sc[2 * bp + 1], aQh[ks], bh[2], bh[3]);
                mma_bf16(sc[2 * bp + 1], aQh[ks], bl[2], bl[3]);
                mma_bf16(sc[2 * bp + 1], aQl[ks], bh[2], bh[3]);
            }
        }

        float nm0 = m0, nm1 = m1;
#pragma unroll
        for (int nt = 0; nt < 16; nt++) {
            int kg = kt + nt * 8 + (lane & 3) * 2;
            sc[nt][0] = (kg     <= qg0 && kg     > qg0 - WIN) ? sc[nt][0] * 0.125f : -1e30f;
            sc[nt][1] = (kg + 1 <= qg0 && kg + 1 > qg0 - WIN) ? sc[nt][1] * 0.125f : -1e30f;
            sc[nt][2] = (kg     <= qg1 && kg     > qg1 - WIN) ? sc[nt][2] * 0.125f : -1e30f;
            sc[nt][3] = (kg + 1 <= qg1 && kg + 1 > qg1 - WIN) ? sc[nt][3] * 0.125f : -1e30f;
            nm0 = fmaxf(nm0, fmaxf(sc[nt][0], sc[nt][1]));
            nm1 = fmaxf(nm1, fmaxf(sc[nt][2], sc[nt][3]));
        }
        nm0 = fmaxf(nm0, __shfl_xor_sync(0xffffffffu, nm0, 1));
        nm0 = fmaxf(nm0, __shfl_xor_sync(0xffffffffu, nm0, 2));
        nm1 = fmaxf(nm1, __shfl_xor_sync(0xffffffffu, nm1, 1));
        nm1 = fmaxf(nm1, __shfl_xor_sync(0xffffffffu, nm1, 2));

        float al0 = __expf(m0 - nm0);
        float al1 = __expf(m1 - nm1);
        m0 = nm0; m1 = nm1;

        float rs0 = 0.0f, rs1 = 0.0f;
#pragma unroll
        for (int nt = 0; nt < 16; nt++) {
            float p0 = (sc[nt][0] > -1e29f) ? __expf(sc[nt][0] - m0) : 0.0f;
            float p1 = (sc[nt][1] > -1e29f) ? __expf(sc[nt][1] - m0) : 0.0f;
            float p2 = (sc[nt][2] > -1e29f) ? __expf(sc[nt][2] - m1) : 0.0f;
            float p3 = (sc[nt][3] > -1e29f) ? __expf(sc[nt][3] - m1) : 0.0f;
            sc[nt][0] = p0; sc[nt][1] = p1; sc[nt][2] = p2; sc[nt][3] = p3;
            rs0 += p0 + p1;
            rs1 += p2 + p3;
        }
        rs0 += __shfl_xor_sync(0xffffffffu, rs0, 1);
        rs0 += __shfl_xor_sync(0xffffffffu, rs0, 2);
        rs1 += __shfl_xor_sync(0xffffffffu, rs1, 1);
        rs1 += __shfl_xor_sync(0xffffffffu, rs1, 2);
        l0 = l0 * al0 + rs0;
        l1 = l1 * al1 + rs1;

#pragma unroll
        for (int i = 0; i < 8; i++) {
            oa[i][0] *= al0; oa[i][1] *= al0;
            oa[i][2] *= al1; oa[i][3] *= al1;
        }

#pragma unroll
        for (int j = 0; j < 8; j++) {
            float p00 = sc[2 * j][0],     p01 = sc[2 * j][1];
            float p02 = sc[2 * j][2],     p03 = sc[2 * j][3];
            float p10 = sc[2 * j + 1][0], p11 = sc[2 * j + 1][1];
            float p12 = sc[2 * j + 1][2], p13 = sc[2 * j + 1][3];
            uint32_t pah[4], pal[4];
            split_pair(p00, p01, pah[0], pal[0]);
            split_pair(p02, p03, pah[1], pal[1]);
            split_pair(p10, p11, pah[2], pal[2]);
            split_pair(p12, p13, pah[3], pal[3]);
#pragma unroll
            for (int dp = 0; dp < 4; dp++) {
                uint32_t bh[4], bl[4];
                int kk = j * 16 + (seg & 1) * 8 + lrow;
                int nn = dp * 16 + (seg >> 1) * 8;
                uint32_t off = (uint32_t)(kk * SKD + nn) * 2;
                ldsm_x4_trans(bh, sb + ATN_V_HI + off);
                ldsm_x4_trans(bl, sb + ATN_V_LO + off);
                mma_bf16(oa[dp * 2],     pah, bh[0], bh[1]);
                mma_bf16(oa[dp * 2],     pah, bl[0], bl[1]);
                mma_bf16(oa[dp * 2],     pal, bh[0], bh[1]);
                mma_bf16(oa[dp * 2 + 1], pah, bh[2], bh[3]);
                mma_bf16(oa[dp * 2 + 1], pah, bl[2], bl[3]);
                mma_bf16(oa[dp * 2 + 1], pal, bh[2], bh[3]);
            }
        }
    }

    // Epilogue: normalize + fused hi/lo split to bf16
    float inv0 = 1.0f / l0;
    float inv1 = 1.0f / l1;
    const int tcol = (lane & 3) * 2;
#pragma unroll
    for (int dt = 0; dt < 8; dt++) {
        size_t c = (size_t)(h * HD + dt * 8 + tcol);
        uint32_t hw0, lw0, hw1, lw1;
        split_pair(oa[dt][0] * inv0, oa[dt][1] * inv0, hw0, lw0);
        split_pair(oa[dt][2] * inv1, oa[dt][3] * inv1, hw1, lw1);
        size_t b0 = (size_t)qg0 * DIM + c;
        size_t b1 = (size_t)qg1 * DIM + c;
        *(uint32_t*)(ohi + b0) = hw0;
        *(uint32_t*)(olo + b0) = lw0;
        *(uint32_t*)(ohi + b1) = hw1;
        *(uint32_t*)(olo + b1) = lw1;
    }
}

// ---------------------------------------------------------------------------
extern "C" void kernel_launch(void* const* d_in, const int* in_sizes, int n_in,
                              void* d_out, int out_size)
{
    const float* x  = (const float*)d_in[0];
    const float* Wq = (const float*)d_in[1];
    const float* Wk = (const float*)d_in[2];
    const float* Wv = (const float*)d_in[3];
    const float* Wo = (const float*)d_in[4];
    float* out = (float*)d_out;

    __nv_bfloat16 *xhi, *xlo, *whi, *wlo;
    __nv_bfloat16 *qhi, *qlo, *khi, *klo, *vhi, *vlo, *ohi, *olo;
    cudaGetSymbolAddress((void**)&xhi, g_xhi);
    cudaGetSymbolAddress((void**)&xlo, g_xlo);
    cudaGetSymbolAddress((void**)&whi, g_whi);
    cudaGetSymbolAddress((void**)&wlo, g_wlo);
    cudaGetSymbolAddress((void**)&qhi, g_qhi);
    cudaGetSymbolAddress((void**)&qlo, g_qlo);
    cudaGetSymbolAddress((void**)&khi, g_khi);
    cudaGetSymbolAddress((void**)&klo, g_klo);
    cudaGetSymbolAddress((void**)&vhi, g_vhi);
    cudaGetSymbolAddress((void**)&vlo, g_vlo);
    cudaGetSymbolAddress((void**)&ohi, g_ohi);
    cudaGetSymbolAddress((void**)&olo, g_olo);

    cudaFuncSetAttribute(gemm_hmma<true>,
                         cudaFuncAttributeMaxDynamicSharedMemorySize, GEMM_SMEM);
    cudaFuncSetAttribute(gemm_hmma<false>,
                         cudaFuncAttributeMaxDynamicSharedMemorySize, GEMM_SMEM);
    cudaFuncSetAttribute(attn_hmma,
                         cudaFuncAttributeMaxDynamicSharedMemorySize, ATN_SMEM);

    // 1) Split x and weights into bf16 hi/lo
    {
        int n4 = S_LEN * DIM / 4;
        split2_kernel<<<(n4 + 255) / 256, 256>>>(x, xhi, xlo, n4);
        int w4 = DIM * DIM / 4;
        split2_kernel<<<(w4 + 255) / 256, 256>>>(Wq, whi + 0 * DIM * DIM, wlo + 0 * DIM * DIM, w4);
        split2_kernel<<<(w4 + 255) / 256, 256>>>(Wk, whi + 1 * DIM * DIM, wlo + 1 * DIM * DIM, w4);
        split2_kernel<<<(w4 + 255) / 256, 256>>>(Wv, whi + 2 * DIM * DIM, wlo + 2 * DIM * DIM, w4);
        split2_kernel<<<(w4 + 255) / 256, 256>>>(Wo, whi + 3 * DIM * DIM, wlo + 3 * DIM * DIM, w4);
    }

    // 2) Fused Q/K/V projections + RoPE + split (HMMA split-fp32)
    gemm_hmma<true><<<dim3(DIM / 128, S_LEN / 128, 3), 256, GEMM_SMEM>>>(
        xhi, xlo, whi, wlo, nullptr,
        qhi, qlo, khi, klo, vhi, vlo);

    // 3) Sliding-window attention (HMMA split-bf16, fused output split)
    attn_hmma<<<dim3(S_LEN / 128, NH), 256, ATN_SMEM>>>(
        qhi, qlo, khi, klo, vhi, vlo, ohi, olo);

    // 4) Output projection (HMMA split-fp32, fp32 out)
    gemm_hmma<false><<<dim3(DIM / 128, S_LEN / 128, 1), 256, GEMM_SMEM>>>(
        ohi, olo, whi + 3 * DIM * DIM, wlo + 3 * DIM * DIM, out,
        nullptr, nullptr, nullptr, nullptr, nullptr, nullptr);
}